// round 1
// baseline (speedup 1.0000x reference)
#include <cuda_runtime.h>
#include <math.h>

// Problem shape (fixed by the dataset): hidden [4,2048,1024] f32, centers [10,1024],
// weights [10], scales [10]. N = 8192 rows, H = 1024, K = 10.
#define H_DIM 1024
#define K_KER 10
#define WARPS_PER_BLOCK 8
#define ROWS_PER_WARP 4
#define MAX_BLOCKS 4096

#define EPS 1e-8f

// Deterministic per-block partial sums (no atomics -> bitwise-stable across replays).
__device__ float g_partials[MAX_BLOCKS];

__global__ __launch_bounds__(WARPS_PER_BLOCK * 32)
void knife_main_kernel(const float* __restrict__ x,
                       const float* __restrict__ centers,
                       const float* __restrict__ weights,
                       const float* __restrict__ scales,
                       int N)
{
    __shared__ float4 sc4[K_KER * (H_DIM / 4)];   // 40 KB: centers staged
    __shared__ float s_csq[K_KER];
    __shared__ float s_w[K_KER];
    __shared__ float s_inv2s2[K_KER];
    __shared__ float warp_sums[WARPS_PER_BLOCK];

    const int tid  = threadIdx.x;
    const int wid  = tid >> 5;
    const int lane = tid & 31;

    // Stage centers into shared (vectorized, coalesced).
    const float4* c4 = reinterpret_cast<const float4*>(centers);
    for (int i = tid; i < K_KER * (H_DIM / 4); i += blockDim.x)
        sc4[i] = c4[i];
    if (tid < K_KER) {
        s_w[tid] = weights[tid];
        float sv = scales[tid];
        s_inv2s2[tid] = 1.0f / (2.0f * sv * sv);
    }
    __syncthreads();

    // ||c_k||^2 per center: one warp per k (warps 0..7 take k=wid, wid+8).
    for (int k = wid; k < K_KER; k += WARPS_PER_BLOCK) {
        float acc = 0.0f;
        for (int i = lane; i < H_DIM / 4; i += 32) {
            float4 v = sc4[k * (H_DIM / 4) + i];
            acc += v.x * v.x + v.y * v.y + v.z * v.z + v.w * v.w;
        }
        #pragma unroll
        for (int o = 16; o; o >>= 1) acc += __shfl_xor_sync(0xFFFFFFFFu, acc, o);
        if (lane == 0) s_csq[k] = acc;
    }
    __syncthreads();

    // Each warp owns ROWS_PER_WARP consecutive rows.
    const int gwarp = blockIdx.x * WARPS_PER_BLOCK + wid;
    const int row0  = gwarp * ROWS_PER_WARP;

    float logsum = 0.0f;

    if (row0 < N) {
        float dot[ROWS_PER_WARP][K_KER];
        float xsq[ROWS_PER_WARP];
        #pragma unroll
        for (int r = 0; r < ROWS_PER_WARP; r++) {
            xsq[r] = 0.0f;
            #pragma unroll
            for (int k = 0; k < K_KER; k++) dot[r][k] = 0.0f;
        }

        const float4* x4 = reinterpret_cast<const float4*>(x);

        #pragma unroll
        for (int j = 0; j < H_DIM / 128; ++j) {       // 8 chunks of 128 floats
            const int col4 = j * 32 + lane;            // float4 index within row
            float4 xv[ROWS_PER_WARP];
            #pragma unroll
            for (int r = 0; r < ROWS_PER_WARP; r++) {
                // rows are guaranteed in-bounds when row0 < N and N % ROWS_PER_WARP == 0;
                // guard anyway for generality
                int row = row0 + r;
                xv[r] = (row < N) ? x4[(size_t)row * (H_DIM / 4) + col4]
                                  : make_float4(0.f, 0.f, 0.f, 0.f);
            }
            #pragma unroll
            for (int r = 0; r < ROWS_PER_WARP; r++)
                xsq[r] += xv[r].x * xv[r].x + xv[r].y * xv[r].y
                        + xv[r].z * xv[r].z + xv[r].w * xv[r].w;
            #pragma unroll
            for (int k = 0; k < K_KER; k++) {
                float4 cv = sc4[k * (H_DIM / 4) + col4];
                #pragma unroll
                for (int r = 0; r < ROWS_PER_WARP; r++)
                    dot[r][k] += xv[r].x * cv.x + xv[r].y * cv.y
                               + xv[r].z * cv.z + xv[r].w * cv.w;
            }
        }

        // Butterfly-reduce all accumulators (every lane ends with the full sum).
        #pragma unroll
        for (int r = 0; r < ROWS_PER_WARP; r++) {
            float v = xsq[r];
            #pragma unroll
            for (int o = 16; o; o >>= 1) v += __shfl_xor_sync(0xFFFFFFFFu, v, o);
            xsq[r] = v;
            #pragma unroll
            for (int k = 0; k < K_KER; k++) {
                float d = dot[r][k];
                #pragma unroll
                for (int o = 16; o; o >>= 1) d += __shfl_xor_sync(0xFFFFFFFFu, d, o);
                dot[r][k] = d;
            }
        }

        if (lane == 0) {
            #pragma unroll
            for (int r = 0; r < ROWS_PER_WARP; r++) {
                int row = row0 + r;
                if (row >= N) break;
                float density = 0.0f;
                #pragma unroll
                for (int k = 0; k < K_KER; k++) {
                    float dsq = xsq[r] + s_csq[k] - 2.0f * dot[r][k];
                    dsq = fmaxf(dsq, 0.0f);
                    density += s_w[k] * expf(-dsq * s_inv2s2[k]);
                }
                logsum += logf(density + EPS);
            }
        }
    }

    // Block reduce -> deterministic partial.
    if (lane == 0) warp_sums[wid] = logsum;
    __syncthreads();
    if (tid == 0) {
        float s = 0.0f;
        #pragma unroll
        for (int wsum = 0; wsum < WARPS_PER_BLOCK; wsum++) s += warp_sums[wsum];
        g_partials[blockIdx.x] = s;
    }
}

__global__ void knife_finalize_kernel(float* __restrict__ out, int nblocks, float invN)
{
    __shared__ float red[256];
    float acc = 0.0f;
    for (int i = threadIdx.x; i < nblocks; i += 256)
        acc += g_partials[i];
    red[threadIdx.x] = acc;
    __syncthreads();
    for (int s = 128; s > 0; s >>= 1) {
        if (threadIdx.x < s) red[threadIdx.x] += red[threadIdx.x + s];
        __syncthreads();
    }
    if (threadIdx.x == 0) {
        float h = -red[0] * invN;            // h_entropy
        float entropy_loss = h;              // BETA = 1.0
        float target_loss  = h * h;          // TARGET_ENTROPY = 0.0
        out[0] = entropy_loss;
        out[1] = target_loss;
        out[2] = entropy_loss + target_loss;
        out[3] = h;
    }
}

extern "C" void kernel_launch(void* const* d_in, const int* in_sizes, int n_in,
                              void* d_out, int out_size)
{
    const float* x       = (const float*)d_in[0];
    const float* centers = (const float*)d_in[1];
    const float* weights = (const float*)d_in[2];
    const float* scales  = (const float*)d_in[3];
    float* out = (float*)d_out;

    const int N = in_sizes[0] / H_DIM;   // 8192 for this problem
    const int rows_per_block = WARPS_PER_BLOCK * ROWS_PER_WARP;  // 32
    int blocks = (N + rows_per_block - 1) / rows_per_block;      // 256
    if (blocks > MAX_BLOCKS) blocks = MAX_BLOCKS;                // shape guard

    knife_main_kernel<<<blocks, WARPS_PER_BLOCK * 32>>>(x, centers, weights, scales, N);
    knife_finalize_kernel<<<1, 256>>>(out, blocks, 1.0f / (float)N);
}

// round 2
// speedup vs baseline: 1.1827x; 1.1827x over previous
#include <cuda_runtime.h>
#include <math.h>

// Shape (fixed by dataset): hidden [4,2048,1024] f32 -> N=8192 rows, H=1024, K=10.
#define H_DIM 1024
#define K_KER 10
#define WARPS_PER_BLOCK 8
#define ROWS_PER_WARP 7
#define ROWS_PER_BLOCK (WARPS_PER_BLOCK * ROWS_PER_WARP)   // 56
#define MAX_BLOCKS 4096
#define EPS 1e-8f

// Deterministic per-block partials + completion counter (reset by last block -> replay-safe).
__device__ float g_partials[MAX_BLOCKS];
__device__ unsigned int g_done = 0;

__global__ __launch_bounds__(WARPS_PER_BLOCK * 32, 1)
void knife_fused_kernel(const float* __restrict__ x,
                        const float* __restrict__ centers,
                        const float* __restrict__ weights,
                        const float* __restrict__ scales,
                        int N, int nblocks, float* __restrict__ out)
{
    __shared__ float4 sc4[K_KER * (H_DIM / 4)];   // 40 KB staged centers
    __shared__ float s_csq[K_KER];
    __shared__ float s_w[K_KER];
    __shared__ float s_inv2s2[K_KER];
    __shared__ float warp_sums[WARPS_PER_BLOCK];
    __shared__ float red[WARPS_PER_BLOCK * 32];

    const int tid  = threadIdx.x;
    const int wid  = tid >> 5;
    const int lane = tid & 31;

    // Stage centers (coalesced float4).
    const float4* c4 = reinterpret_cast<const float4*>(centers);
    for (int i = tid; i < K_KER * (H_DIM / 4); i += blockDim.x)
        sc4[i] = c4[i];
    if (tid < K_KER) {
        s_w[tid] = weights[tid];
        float sv = scales[tid];
        s_inv2s2[tid] = 1.0f / (2.0f * sv * sv);
    }
    __syncthreads();

    // ||c_k||^2: one warp per k.
    for (int k = wid; k < K_KER; k += WARPS_PER_BLOCK) {
        float acc = 0.0f;
        for (int i = lane; i < H_DIM / 4; i += 32) {
            float4 v = sc4[k * (H_DIM / 4) + i];
            acc += v.x * v.x + v.y * v.y + v.z * v.z + v.w * v.w;
        }
        #pragma unroll
        for (int o = 16; o; o >>= 1) acc += __shfl_xor_sync(0xFFFFFFFFu, acc, o);
        if (lane == 0) s_csq[k] = acc;
    }
    __syncthreads();

    // Each warp owns ROWS_PER_WARP consecutive rows. 147 blocks * 56 rows covers 8192 (+guard).
    const int gwarp = blockIdx.x * WARPS_PER_BLOCK + wid;
    const int row0  = gwarp * ROWS_PER_WARP;
    const int nrows = (row0 < N) ? min(ROWS_PER_WARP, N - row0) : 0;

    float dot[ROWS_PER_WARP][K_KER];
    float xsq[ROWS_PER_WARP];
    #pragma unroll
    for (int r = 0; r < ROWS_PER_WARP; r++) {
        xsq[r] = 0.0f;
        #pragma unroll
        for (int k = 0; k < K_KER; k++) dot[r][k] = 0.0f;
    }

    const float4* x4 = reinterpret_cast<const float4*>(x);

    if (nrows == ROWS_PER_WARP) {
        // Fast path: all rows valid, no per-load predication.
        #pragma unroll
        for (int j = 0; j < H_DIM / 128; ++j) {
            const int col4 = j * 32 + lane;
            float4 xv[ROWS_PER_WARP];
            #pragma unroll
            for (int r = 0; r < ROWS_PER_WARP; r++)
                xv[r] = x4[(size_t)(row0 + r) * (H_DIM / 4) + col4];
            #pragma unroll
            for (int r = 0; r < ROWS_PER_WARP; r++)
                xsq[r] += xv[r].x * xv[r].x + xv[r].y * xv[r].y
                        + xv[r].z * xv[r].z + xv[r].w * xv[r].w;
            #pragma unroll
            for (int k = 0; k < K_KER; k++) {
                float4 cv = sc4[k * (H_DIM / 4) + col4];
                #pragma unroll
                for (int r = 0; r < ROWS_PER_WARP; r++)
                    dot[r][k] += xv[r].x * cv.x + xv[r].y * cv.y
                               + xv[r].z * cv.z + xv[r].w * cv.w;
            }
        }
    } else if (nrows > 0) {
        #pragma unroll
        for (int j = 0; j < H_DIM / 128; ++j) {
            const int col4 = j * 32 + lane;
            float4 xv[ROWS_PER_WARP];
            #pragma unroll
            for (int r = 0; r < ROWS_PER_WARP; r++)
                xv[r] = (r < nrows) ? x4[(size_t)(row0 + r) * (H_DIM / 4) + col4]
                                    : make_float4(0.f, 0.f, 0.f, 0.f);
            #pragma unroll
            for (int r = 0; r < ROWS_PER_WARP; r++)
                xsq[r] += xv[r].x * xv[r].x + xv[r].y * xv[r].y
                        + xv[r].z * xv[r].z + xv[r].w * xv[r].w;
            #pragma unroll
            for (int k = 0; k < K_KER; k++) {
                float4 cv = sc4[k * (H_DIM / 4) + col4];
                #pragma unroll
                for (int r = 0; r < ROWS_PER_WARP; r++)
                    dot[r][k] += xv[r].x * cv.x + xv[r].y * cv.y
                               + xv[r].z * cv.z + xv[r].w * cv.w;
            }
        }
    }

    // Butterfly-reduce accumulators: every lane ends with full sums.
    #pragma unroll
    for (int r = 0; r < ROWS_PER_WARP; r++) {
        float v = xsq[r];
        #pragma unroll
        for (int o = 16; o; o >>= 1) v += __shfl_xor_sync(0xFFFFFFFFu, v, o);
        xsq[r] = v;
        #pragma unroll
        for (int k = 0; k < K_KER; k++) {
            float d = dot[r][k];
            #pragma unroll
            for (int o = 16; o; o >>= 1) d += __shfl_xor_sync(0xFFFFFFFFu, d, o);
            dot[r][k] = d;
        }
    }

    // Parallel epilogue: lane r handles row r.
    float logsum = 0.0f;
    if (lane < nrows) {
        float density = 0.0f;
        #pragma unroll
        for (int k = 0; k < K_KER; k++) {
            // sums are uniform across lanes; pick via lane index (compile-time select chain).
            float xq = 0.f, dt = 0.f;
            #pragma unroll
            for (int r = 0; r < ROWS_PER_WARP; r++)
                if (lane == r) { xq = xsq[r]; dt = dot[r][k]; }
            float dsq = fmaxf(xq + s_csq[k] - 2.0f * dt, 0.0f);
            density += s_w[k] * expf(-dsq * s_inv2s2[k]);
        }
        logsum = logf(density + EPS);
    }
    #pragma unroll
    for (int o = 16; o; o >>= 1) logsum += __shfl_xor_sync(0xFFFFFFFFu, logsum, o);

    if (lane == 0) warp_sums[wid] = logsum;
    __syncthreads();
    if (tid == 0) {
        float s = 0.0f;
        #pragma unroll
        for (int w = 0; w < WARPS_PER_BLOCK; w++) s += warp_sums[w];
        g_partials[blockIdx.x] = s;
    }

    // ── Fused finalize: last block to finish reduces all partials. ──
    __shared__ unsigned int s_is_last;
    __threadfence();
    __syncthreads();
    if (tid == 0) {
        unsigned int prev = atomicAdd(&g_done, 1u);
        s_is_last = (prev == (unsigned int)(nblocks - 1)) ? 1u : 0u;
    }
    __syncthreads();
    if (s_is_last) {
        float acc = 0.0f;
        for (int i = tid; i < nblocks; i += blockDim.x)
            acc += g_partials[i];
        red[tid] = acc;
        __syncthreads();
        for (int s = (WARPS_PER_BLOCK * 32) / 2; s > 0; s >>= 1) {
            if (tid < s) red[tid] += red[tid + s];
            __syncthreads();
        }
        if (tid == 0) {
            float h = -red[0] / (float)N;     // h_entropy
            float entropy_loss = h;           // BETA = 1.0
            float target_loss  = h * h;       // TARGET_ENTROPY = 0.0
            out[0] = entropy_loss;
            out[1] = target_loss;
            out[2] = entropy_loss + target_loss;
            out[3] = h;
            g_done = 0;                       // reset for next graph replay
        }
    }
}

extern "C" void kernel_launch(void* const* d_in, const int* in_sizes, int n_in,
                              void* d_out, int out_size)
{
    const float* x       = (const float*)d_in[0];
    const float* centers = (const float*)d_in[1];
    const float* weights = (const float*)d_in[2];
    const float* scales  = (const float*)d_in[3];
    float* out = (float*)d_out;

    const int N = in_sizes[0] / H_DIM;                       // 8192
    int blocks = (N + ROWS_PER_BLOCK - 1) / ROWS_PER_BLOCK;  // 147 -> one wave on 148 SMs
    if (blocks > MAX_BLOCKS) blocks = MAX_BLOCKS;

    knife_fused_kernel<<<blocks, WARPS_PER_BLOCK * 32>>>(x, centers, weights, scales,
                                                         N, blocks, out);
}

// round 4
// speedup vs baseline: 1.2749x; 1.0779x over previous
#include <cuda_runtime.h>
#include <math.h>

// Shape (fixed by dataset): hidden [4,2048,1024] f32 -> N=8192 rows, H=1024, K=10.
#define H_DIM 1024
#define K_KER 10
#define WARPS_PER_BLOCK 14
#define THREADS (WARPS_PER_BLOCK * 32)          // 448
#define ROWS_PER_WARP 4
#define ROWS_PER_BLOCK (WARPS_PER_BLOCK * ROWS_PER_WARP)   // 56
#define MAX_BLOCKS 4096
#define EPS 1e-8f

__device__ float g_partials[MAX_BLOCKS];
__device__ unsigned int g_done = 0;

// Packed f32x2 FMA / helpers (Blackwell: only reachable via PTX).
__device__ __forceinline__ unsigned long long fma2(unsigned long long a,
                                                   unsigned long long b,
                                                   unsigned long long c) {
    unsigned long long d;
    asm("fma.rn.f32x2 %0, %1, %2, %3;" : "=l"(d) : "l"(a), "l"(b), "l"(c));
    return d;
}
__device__ __forceinline__ float lo_f(unsigned long long v) {
    return __uint_as_float((unsigned int)(v & 0xffffffffull));
}
__device__ __forceinline__ float hi_f(unsigned long long v) {
    return __uint_as_float((unsigned int)(v >> 32));
}

// Warp all-reduce add via butterfly (redux.f32 NOT supported on sm_103).
__device__ __forceinline__ float warp_sum(float v) {
    #pragma unroll
    for (int o = 16; o; o >>= 1) v += __shfl_xor_sync(0xFFFFFFFFu, v, o);
    return v;
}

__global__ __launch_bounds__(THREADS, 1)
void knife_fused_kernel(const float* __restrict__ x,
                        const float* __restrict__ centers,
                        const float* __restrict__ weights,
                        const float* __restrict__ scales,
                        int N, int nblocks, float* __restrict__ out)
{
    // Centers staged as ulonglong2 (16B = 4 floats, bit-identical to float4).
    __shared__ ulonglong2 sc2[K_KER * (H_DIM / 4)];   // 40 KB
    __shared__ float s_csq[K_KER];
    __shared__ float s_w[K_KER];
    __shared__ float s_inv2s2[K_KER];
    __shared__ float warp_sums[WARPS_PER_BLOCK];

    const int tid  = threadIdx.x;
    const int wid  = tid >> 5;
    const int lane = tid & 31;

    // Stage centers (coalesced 16B).
    const ulonglong2* c2 = reinterpret_cast<const ulonglong2*>(centers);
    for (int i = tid; i < K_KER * (H_DIM / 4); i += THREADS)
        sc2[i] = c2[i];
    if (tid < K_KER) {
        s_w[tid] = weights[tid];
        float sv = scales[tid];
        s_inv2s2[tid] = 1.0f / (2.0f * sv * sv);
    }
    __syncthreads();

    // ||c_k||^2: one warp per k.
    for (int k = wid; k < K_KER; k += WARPS_PER_BLOCK) {
        float acc = 0.0f;
        for (int i = lane; i < H_DIM / 4; i += 32) {
            ulonglong2 v = sc2[k * (H_DIM / 4) + i];
            float a = lo_f(v.x), b = hi_f(v.x), cc = lo_f(v.y), d = hi_f(v.y);
            acc += a * a + b * b + cc * cc + d * d;
        }
        acc = warp_sum(acc);
        if (lane == 0) s_csq[k] = acc;
    }
    __syncthreads();

    // Each warp owns ROWS_PER_WARP consecutive rows; 147 blocks * 56 = 8232 >= 8192.
    const int gwarp = blockIdx.x * WARPS_PER_BLOCK + wid;
    const int row0  = gwarp * ROWS_PER_WARP;
    const int nrows = (row0 < N) ? min(ROWS_PER_WARP, N - row0) : 0;

    // Packed accumulators: each ull holds two partial sums (even/odd float pairs).
    unsigned long long dot2[ROWS_PER_WARP][K_KER];
    unsigned long long xsq2[ROWS_PER_WARP];
    #pragma unroll
    for (int r = 0; r < ROWS_PER_WARP; r++) {
        xsq2[r] = 0ull;
        #pragma unroll
        for (int k = 0; k < K_KER; k++) dot2[r][k] = 0ull;
    }

    const ulonglong2* x2 = reinterpret_cast<const ulonglong2*>(x);

    if (nrows == ROWS_PER_WARP) {
        #pragma unroll
        for (int j = 0; j < H_DIM / 128; ++j) {
            const int col4 = j * 32 + lane;
            ulonglong2 xv[ROWS_PER_WARP];
            #pragma unroll
            for (int r = 0; r < ROWS_PER_WARP; r++)
                xv[r] = x2[(size_t)(row0 + r) * (H_DIM / 4) + col4];
            #pragma unroll
            for (int r = 0; r < ROWS_PER_WARP; r++) {
                xsq2[r] = fma2(xv[r].x, xv[r].x, xsq2[r]);
                xsq2[r] = fma2(xv[r].y, xv[r].y, xsq2[r]);
            }
            #pragma unroll
            for (int k = 0; k < K_KER; k++) {
                ulonglong2 cv = sc2[k * (H_DIM / 4) + col4];
                #pragma unroll
                for (int r = 0; r < ROWS_PER_WARP; r++) {
                    dot2[r][k] = fma2(xv[r].x, cv.x, dot2[r][k]);
                    dot2[r][k] = fma2(xv[r].y, cv.y, dot2[r][k]);
                }
            }
        }
    } else if (nrows > 0) {
        #pragma unroll
        for (int j = 0; j < H_DIM / 128; ++j) {
            const int col4 = j * 32 + lane;
            ulonglong2 xv[ROWS_PER_WARP];
            #pragma unroll
            for (int r = 0; r < ROWS_PER_WARP; r++) {
                if (r < nrows) xv[r] = x2[(size_t)(row0 + r) * (H_DIM / 4) + col4];
                else { xv[r].x = 0ull; xv[r].y = 0ull; }
            }
            #pragma unroll
            for (int r = 0; r < ROWS_PER_WARP; r++) {
                xsq2[r] = fma2(xv[r].x, xv[r].x, xsq2[r]);
                xsq2[r] = fma2(xv[r].y, xv[r].y, xsq2[r]);
            }
            #pragma unroll
            for (int k = 0; k < K_KER; k++) {
                ulonglong2 cv = sc2[k * (H_DIM / 4) + col4];
                #pragma unroll
                for (int r = 0; r < ROWS_PER_WARP; r++) {
                    dot2[r][k] = fma2(xv[r].x, cv.x, dot2[r][k]);
                    dot2[r][k] = fma2(xv[r].y, cv.y, dot2[r][k]);
                }
            }
        }
    }

    // Collapse packed halves, then butterfly-reduce across lanes.
    float dot[ROWS_PER_WARP][K_KER];
    float xsq[ROWS_PER_WARP];
    #pragma unroll
    for (int r = 0; r < ROWS_PER_WARP; r++) {
        xsq[r] = warp_sum(lo_f(xsq2[r]) + hi_f(xsq2[r]));
        #pragma unroll
        for (int k = 0; k < K_KER; k++)
            dot[r][k] = warp_sum(lo_f(dot2[r][k]) + hi_f(dot2[r][k]));
    }

    // Parallel epilogue: lane r handles row r.
    float logsum = 0.0f;
    if (lane < nrows) {
        float xq = 0.f;
        #pragma unroll
        for (int r = 0; r < ROWS_PER_WARP; r++)
            if (lane == r) xq = xsq[r];
        float density = 0.0f;
        #pragma unroll
        for (int k = 0; k < K_KER; k++) {
            float dt = 0.f;
            #pragma unroll
            for (int r = 0; r < ROWS_PER_WARP; r++)
                if (lane == r) dt = dot[r][k];
            float dsq = fmaxf(xq + s_csq[k] - 2.0f * dt, 0.0f);
            density += s_w[k] * expf(-dsq * s_inv2s2[k]);
        }
        logsum = logf(density + EPS);
    }
    logsum = warp_sum(logsum);

    if (lane == 0) warp_sums[wid] = logsum;
    __syncthreads();
    if (tid == 0) {
        float s = 0.0f;
        #pragma unroll
        for (int w = 0; w < WARPS_PER_BLOCK; w++) s += warp_sums[w];
        g_partials[blockIdx.x] = s;
    }

    // ── Fused finalize: last block reduces all partials. ──
    __shared__ unsigned int s_is_last;
    __shared__ float red[WARPS_PER_BLOCK];
    __threadfence();
    __syncthreads();
    if (tid == 0) {
        unsigned int prev = atomicAdd(&g_done, 1u);
        s_is_last = (prev == (unsigned int)(nblocks - 1)) ? 1u : 0u;
    }
    __syncthreads();
    if (s_is_last) {
        float acc = 0.0f;
        for (int i = tid; i < nblocks; i += THREADS)
            acc += g_partials[i];
        acc = warp_sum(acc);
        if (lane == 0) red[wid] = acc;
        __syncthreads();
        if (tid == 0) {
            float s = 0.0f;
            #pragma unroll
            for (int w = 0; w < WARPS_PER_BLOCK; w++) s += red[w];
            float h = -s / (float)N;          // h_entropy
            float entropy_loss = h;           // BETA = 1.0
            float target_loss  = h * h;       // TARGET_ENTROPY = 0.0
            out[0] = entropy_loss;
            out[1] = target_loss;
            out[2] = entropy_loss + target_loss;
            out[3] = h;
            g_done = 0;                       // reset for next graph replay
        }
    }
}

extern "C" void kernel_launch(void* const* d_in, const int* in_sizes, int n_in,
                              void* d_out, int out_size)
{
    const float* x       = (const float*)d_in[0];
    const float* centers = (const float*)d_in[1];
    const float* weights = (const float*)d_in[2];
    const float* scales  = (const float*)d_in[3];
    float* out = (float*)d_out;

    const int N = in_sizes[0] / H_DIM;                       // 8192
    int blocks = (N + ROWS_PER_BLOCK - 1) / ROWS_PER_BLOCK;  // 147 -> one wave on 148 SMs
    if (blocks > MAX_BLOCKS) blocks = MAX_BLOCKS;

    knife_fused_kernel<<<blocks, THREADS>>>(x, centers, weights, scales, N, blocks, out);
}